// round 11
// baseline (speedup 1.0000x reference)
#include <cuda_runtime.h>
#include <cuda_fp16.h>
#include <stdint.h>

#define BATCH   4096
#define IN_DIM  16384
#define OUT_DIM 16384
#define THREADS 1024
#define NCONS   768               // consumer threads (warps 0-23)
#define NPROD   256               // producer threads (warps 24-31)
#define PAIRS   (BATCH / 2)       // 2048

// Per-j k coefficients, 8B: x = half2(k0,k1), y = half2(k2,k3)
__device__ uint2    g_k8[OUT_DIM];
// Per-j packed indices: a | (b<<16)
__device__ uint32_t g_idx_pack[OUT_DIM];
// Dynamic work queue counter
__device__ int g_ctr;

__constant__ float c_gate[16][4] = {
    {0.f, 0.f, 0.f, 0.f}, {0.f, 0.f, 0.f, 1.f}, {0.f, 1.f, 0.f,-1.f}, {0.f, 1.f, 0.f, 0.f},
    {0.f, 0.f, 1.f,-1.f}, {0.f, 0.f, 1.f, 0.f}, {0.f, 1.f, 1.f,-2.f}, {0.f, 1.f, 1.f,-1.f},
    {1.f,-1.f,-1.f, 1.f}, {1.f,-1.f,-1.f, 2.f}, {1.f, 0.f,-1.f, 0.f}, {1.f, 0.f,-1.f, 1.f},
    {1.f,-1.f, 0.f, 0.f}, {1.f,-1.f, 0.f, 1.f}, {1.f, 0.f, 0.f,-1.f}, {1.f, 0.f, 0.f, 0.f}
};

// int64-vs-int32 buffer detection (R1 fix).
__device__ __forceinline__ bool idx_is_int64(const int* p) {
    bool odd_all_zero = true;
    #pragma unroll
    for (int i = 1; i < 64; i += 2) odd_all_zero &= (p[i] == 0);
    return odd_all_zero;
}
__device__ __forceinline__ int load_index(const void* base, int j, bool is64) {
    if (is64) return (int)((const long long*)base)[j];
    return ((const int*)base)[j];
}

__global__ void prep_kernel(const float* __restrict__ w,
                            const void* __restrict__ a_idx,
                            const void* __restrict__ b_idx,
                            int ncta)
{
    int j = blockIdx.x * blockDim.x + threadIdx.x;
    if (j == 0) g_ctr = ncta;   // first ncta pairs statically assigned
    if (j >= OUT_DIM) return;

    const bool a64 = idx_is_int64((const int*)a_idx);
    const bool b64 = idx_is_int64((const int*)b_idx);

    float wv[16];
    const float4* w4 = reinterpret_cast<const float4*>(w + (size_t)j * 16);
    #pragma unroll
    for (int q = 0; q < 4; q++) {
        float4 v = __ldg(&w4[q]);
        wv[q*4+0] = v.x; wv[q*4+1] = v.y; wv[q*4+2] = v.z; wv[q*4+3] = v.w;
    }
    float m = wv[0];
    #pragma unroll
    for (int i = 1; i < 16; i++) m = fmaxf(m, wv[i]);
    float e[16], s = 0.f;
    #pragma unroll
    for (int i = 0; i < 16; i++) { e[i] = __expf(wv[i] - m); s += e[i]; }
    float inv = 1.0f / s;

    float k0 = 0.f, k1 = 0.f, k2 = 0.f, k3 = 0.f;
    #pragma unroll
    for (int i = 0; i < 16; i++) {
        float p = e[i] * inv;
        k0 = fmaf(p, c_gate[i][0], k0);
        k1 = fmaf(p, c_gate[i][1], k1);
        k2 = fmaf(p, c_gate[i][2], k2);
        k3 = fmaf(p, c_gate[i][3], k3);
    }

    unsigned int ia = (unsigned int)load_index(a_idx, j, a64);
    unsigned int ib = (unsigned int)load_index(b_idx, j, b64);

    __half2 h01 = __floats2half2_rn(k0, k1);
    __half2 h23 = __floats2half2_rn(k2, k3);
    uint2 k8;
    k8.x = *reinterpret_cast<unsigned int*>(&h01);
    k8.y = *reinterpret_cast<unsigned int*>(&h23);
    g_k8[j] = k8;
    g_idx_pack[j] = ia | (ib << 16);
}

// Stage a pair (2 fp32 rows) into an interleaved half2 slot with NT threads.
template <int NT>
__device__ __forceinline__ void stage_pair(const float* __restrict__ r0,
                                           __half2* __restrict__ dst, int t)
{
    #pragma unroll
    for (int it = 0; it < (IN_DIM / 4) / NT; it++) {
        int k = (t + it * NT) * 4;
        float4 e = __ldcg(reinterpret_cast<const float4*>(r0 + k));
        float4 o = __ldcg(reinterpret_cast<const float4*>(r0 + IN_DIM + k));
        __half2 h0 = __floats2half2_rn(e.x, o.x);
        __half2 h1 = __floats2half2_rn(e.y, o.y);
        __half2 h2 = __floats2half2_rn(e.z, o.z);
        __half2 h3 = __floats2half2_rn(e.w, o.w);
        uint4 pk;
        pk.x = *reinterpret_cast<unsigned int*>(&h0);
        pk.y = *reinterpret_cast<unsigned int*>(&h1);
        pk.z = *reinterpret_cast<unsigned int*>(&h2);
        pk.w = *reinterpret_cast<unsigned int*>(&h3);
        *reinterpret_cast<uint4*>(dst + k) = pk;
    }
}

// Evaluate one j for both rows of the pair.
__device__ __forceinline__ void eval2(uint32_t idxp, uint32_t k01u, uint32_t k23u,
                                      const __half2* __restrict__ xs,
                                      float& ve, float& vo)
{
    float2 k01 = __half22float2(*reinterpret_cast<__half2*>(&k01u));  // k0,k1
    float2 k23 = __half22float2(*reinterpret_cast<__half2*>(&k23u));  // k2,k3
    float2 a = __half22float2(xs[idxp & 0xFFFFu]);
    float2 b = __half22float2(xs[idxp >> 16]);
    ve = fmaf(a.x, fmaf(k23.y, b.x, k01.y), fmaf(k23.x, b.x, k01.x));
    vo = fmaf(a.y, fmaf(k23.y, b.y, k01.y), fmaf(k23.x, b.y, k01.x));
}

// Warp-specialized persistent kernel, 1 CTA/SM, 1024 threads.
// smem: two 64KB pair-interleaved half2 slots (true double buffer).
// Warps 24-31 (256 thr) stage the NEXT pair into buf[s^1] while
// warps 0-23 (768 thr) compute the CURRENT pair from buf[s].
// One __syncthreads per pair; dynamic queue with parity-indexed handoff.
__global__ void __launch_bounds__(THREADS, 1)
logic_main_kernel(const float* __restrict__ x, float* __restrict__ out)
{
    extern __shared__ __align__(16) unsigned char smem_raw[];
    __half2* buf[2] = {
        reinterpret_cast<__half2*>(smem_raw),
        reinterpret_cast<__half2*>(smem_raw + IN_DIM * sizeof(__half2))
    };
    __shared__ int s_next[2];

    const int tid = threadIdx.x;
    int cur = blockIdx.x;

    // Prologue: all 1024 threads stage the first pair into buf[0]; pop next.
    stage_pair<THREADS>(x + (size_t)(2 * cur) * IN_DIM, buf[0], tid);
    if (tid == 0) s_next[0] = atomicAdd(&g_ctr, 1);
    __syncthreads();

    int s = 0, pi = 0;
    while (cur < PAIRS) {
        const int nxt = s_next[pi];

        if (tid < NCONS) {
            // ---- consumers: compute both rows of `cur` from buf[s] ----
            const __half2* __restrict__ xs = buf[s];
            float* __restrict__ oe = out + (size_t)(2 * cur) * OUT_DIM;
            float* __restrict__ oo = oe + OUT_DIM;

            #pragma unroll 4
            for (int j0 = 2 * tid; j0 < OUT_DIM; j0 += 2 * NCONS) {
                uint2 I = __ldg(reinterpret_cast<const uint2*>(&g_idx_pack[j0]));
                uint4 K = __ldg(reinterpret_cast<const uint4*>(&g_k8[j0]));

                float2 ve, vo;
                eval2(I.x, K.x, K.y, xs, ve.x, vo.x);
                eval2(I.y, K.z, K.w, xs, ve.y, vo.y);

                __stcs(reinterpret_cast<float2*>(&oe[j0]), ve);
                __stcs(reinterpret_cast<float2*>(&oo[j0]), vo);
            }
        } else {
            // ---- producers: stage `nxt` into buf[s^1] ----
            if (nxt < PAIRS)
                stage_pair<NPROD>(x + (size_t)(2 * nxt) * IN_DIM, buf[s ^ 1], tid - NCONS);
        }

        // Pop the pair for the iteration after next (parity slot avoids races).
        if (tid == 0) s_next[pi ^ 1] = atomicAdd(&g_ctr, 1);
        __syncthreads();

        cur = nxt;
        s ^= 1;
        pi ^= 1;
    }
}

extern "C" void kernel_launch(void* const* d_in, const int* in_sizes, int n_in,
                              void* d_out, int out_size)
{
    const float* x  = (const float*)d_in[0];
    const float* w  = (const float*)d_in[1];
    const void*  ai = d_in[2];
    const void*  bi = d_in[3];
    float* out = (float*)d_out;
    (void)in_sizes; (void)n_in; (void)out_size;

    int nsm = 148;
    cudaDeviceGetAttribute(&nsm, cudaDevAttrMultiProcessorCount, 0);
    const int ncta = nsm;   // 1 CTA per SM

    const int smem_bytes = 2 * IN_DIM * sizeof(__half2);   // 128KB per CTA
    cudaFuncSetAttribute(logic_main_kernel,
                         cudaFuncAttributeMaxDynamicSharedMemorySize, smem_bytes);

    prep_kernel<<<(OUT_DIM + 511) / 512, 512>>>(w, ai, bi, ncta);
    logic_main_kernel<<<ncta, THREADS, smem_bytes>>>(x, out);
}

// round 12
// speedup vs baseline: 1.5986x; 1.5986x over previous
#include <cuda_runtime.h>
#include <cuda_fp16.h>
#include <stdint.h>

#define BATCH   4096
#define IN_DIM  16384
#define OUT_DIM 16384
#define THREADS 1024
#define PAIRS   (BATCH / 2)       // 2048
#define NGROUP  8                 // compute groups per pair (2 j per thread each)
#define NSTAGE  4                 // stage sub-iterations per pair

// Per-j k coefficients, 8B: x = half2(k0,k1), y = half2(k2,k3)
__device__ uint2    g_k8[OUT_DIM];
// Per-j packed indices: a | (b<<16)
__device__ uint32_t g_idx_pack[OUT_DIM];
// Dynamic work queue counter
__device__ int g_ctr;

__constant__ float c_gate[16][4] = {
    {0.f, 0.f, 0.f, 0.f}, {0.f, 0.f, 0.f, 1.f}, {0.f, 1.f, 0.f,-1.f}, {0.f, 1.f, 0.f, 0.f},
    {0.f, 0.f, 1.f,-1.f}, {0.f, 0.f, 1.f, 0.f}, {0.f, 1.f, 1.f,-2.f}, {0.f, 1.f, 1.f,-1.f},
    {1.f,-1.f,-1.f, 1.f}, {1.f,-1.f,-1.f, 2.f}, {1.f, 0.f,-1.f, 0.f}, {1.f, 0.f,-1.f, 1.f},
    {1.f,-1.f, 0.f, 0.f}, {1.f,-1.f, 0.f, 1.f}, {1.f, 0.f, 0.f,-1.f}, {1.f, 0.f, 0.f, 0.f}
};

// int64-vs-int32 buffer detection (R1 fix).
__device__ __forceinline__ bool idx_is_int64(const int* p) {
    bool odd_all_zero = true;
    #pragma unroll
    for (int i = 1; i < 64; i += 2) odd_all_zero &= (p[i] == 0);
    return odd_all_zero;
}
__device__ __forceinline__ int load_index(const void* base, int j, bool is64) {
    if (is64) return (int)((const long long*)base)[j];
    return ((const int*)base)[j];
}

__global__ void prep_kernel(const float* __restrict__ w,
                            const void* __restrict__ a_idx,
                            const void* __restrict__ b_idx,
                            int ncta)
{
    int j = blockIdx.x * blockDim.x + threadIdx.x;
    if (j == 0) g_ctr = ncta;   // first ncta pairs statically assigned
    if (j >= OUT_DIM) return;

    const bool a64 = idx_is_int64((const int*)a_idx);
    const bool b64 = idx_is_int64((const int*)b_idx);

    float wv[16];
    const float4* w4 = reinterpret_cast<const float4*>(w + (size_t)j * 16);
    #pragma unroll
    for (int q = 0; q < 4; q++) {
        float4 v = __ldg(&w4[q]);
        wv[q*4+0] = v.x; wv[q*4+1] = v.y; wv[q*4+2] = v.z; wv[q*4+3] = v.w;
    }
    float m = wv[0];
    #pragma unroll
    for (int i = 1; i < 16; i++) m = fmaxf(m, wv[i]);
    float e[16], s = 0.f;
    #pragma unroll
    for (int i = 0; i < 16; i++) { e[i] = __expf(wv[i] - m); s += e[i]; }
    float inv = 1.0f / s;

    float k0 = 0.f, k1 = 0.f, k2 = 0.f, k3 = 0.f;
    #pragma unroll
    for (int i = 0; i < 16; i++) {
        float p = e[i] * inv;
        k0 = fmaf(p, c_gate[i][0], k0);
        k1 = fmaf(p, c_gate[i][1], k1);
        k2 = fmaf(p, c_gate[i][2], k2);
        k3 = fmaf(p, c_gate[i][3], k3);
    }

    unsigned int ia = (unsigned int)load_index(a_idx, j, a64);
    unsigned int ib = (unsigned int)load_index(b_idx, j, b64);

    __half2 h01 = __floats2half2_rn(k0, k1);
    __half2 h23 = __floats2half2_rn(k2, k3);
    uint2 k8;
    k8.x = *reinterpret_cast<unsigned int*>(&h01);
    k8.y = *reinterpret_cast<unsigned int*>(&h23);
    g_k8[j] = k8;
    g_idx_pack[j] = ia | (ib << 16);
}

// Evaluate one j for both rows of the pair.
__device__ __forceinline__ void eval2(uint32_t idxp, uint32_t k01u, uint32_t k23u,
                                      const __half2* __restrict__ xs,
                                      float& ve, float& vo)
{
    float2 k01 = __half22float2(*reinterpret_cast<__half2*>(&k01u));  // k0,k1
    float2 k23 = __half22float2(*reinterpret_cast<__half2*>(&k23u));  // k2,k3
    float2 a = __half22float2(xs[idxp & 0xFFFFu]);
    float2 b = __half22float2(xs[idxp >> 16]);
    ve = fmaf(a.x, fmaf(k23.y, b.x, k01.y), fmaf(k23.x, b.x, k01.x));
    vo = fmaf(a.y, fmaf(k23.y, b.y, k01.y), fmaf(k23.x, b.y, k01.x));
}

// Software-pipelined persistent kernel, 1 CTA/SM, 1024 threads,
// double buffer 2 x 64KB pair-interleaved half2 slots.
// Per iteration g: (1) issue next-pair stage LDGs, (2) compute current-pair
// group g (covers the stage-load latency), (3) convert+STS the staged regs.
// Same warps do staging and compute -> no phase serialization, full MLP.
__global__ void __launch_bounds__(THREADS, 1)
logic_main_kernel(const float* __restrict__ x, float* __restrict__ out)
{
    extern __shared__ __align__(16) unsigned char smem_raw[];
    __half2* buf[2] = {
        reinterpret_cast<__half2*>(smem_raw),
        reinterpret_cast<__half2*>(smem_raw + IN_DIM * sizeof(__half2))
    };
    __shared__ int s_next[2];

    const int tid = threadIdx.x;
    int cur = blockIdx.x;

    // Prologue: stage pair `cur` into buf[0] with all threads; pop next.
    {
        const float* __restrict__ r0 = x + (size_t)(2 * cur) * IN_DIM;
        #pragma unroll
        for (int it = 0; it < NSTAGE; it++) {
            int k = (tid + it * THREADS) * 4;
            float4 e = __ldcg(reinterpret_cast<const float4*>(r0 + k));
            float4 o = __ldcg(reinterpret_cast<const float4*>(r0 + IN_DIM + k));
            __half2 h0 = __floats2half2_rn(e.x, o.x);
            __half2 h1 = __floats2half2_rn(e.y, o.y);
            __half2 h2 = __floats2half2_rn(e.z, o.z);
            __half2 h3 = __floats2half2_rn(e.w, o.w);
            uint4 pk;
            pk.x = *reinterpret_cast<unsigned int*>(&h0);
            pk.y = *reinterpret_cast<unsigned int*>(&h1);
            pk.z = *reinterpret_cast<unsigned int*>(&h2);
            pk.w = *reinterpret_cast<unsigned int*>(&h3);
            *reinterpret_cast<uint4*>(buf[0] + k) = pk;
        }
    }
    if (tid == 0) s_next[0] = atomicAdd(&g_ctr, 1);
    __syncthreads();

    int s = 0, pi = 0;
    while (cur < PAIRS) {
        const int nxt = s_next[pi];
        const bool do_stage = (nxt < PAIRS);

        const __half2* __restrict__ xs  = buf[s];
        __half2*       __restrict__ dst = buf[s ^ 1];
        const float*   __restrict__ rn  = x + (size_t)(2 * (do_stage ? nxt : cur)) * IN_DIM;
        float* __restrict__ oe = out + (size_t)(2 * cur) * OUT_DIM;
        float* __restrict__ oo = oe + OUT_DIM;

        #pragma unroll
        for (int g = 0; g < NGROUP; g++) {
            // (1) stage loads for next pair (first NSTAGE groups)
            float4 se, so;
            int sk = 0;
            if (do_stage && g < NSTAGE) {
                sk = (tid + g * THREADS) * 4;
                se = __ldcg(reinterpret_cast<const float4*>(rn + sk));
                so = __ldcg(reinterpret_cast<const float4*>(rn + IN_DIM + sk));
            }

            // (2) compute group g of current pair (covers stage-load latency)
            const int j0 = g * (OUT_DIM / NGROUP) + tid * 2;
            uint2 I = __ldg(reinterpret_cast<const uint2*>(&g_idx_pack[j0]));
            uint4 K = __ldg(reinterpret_cast<const uint4*>(&g_k8[j0]));

            float2 ve, vo;
            eval2(I.x, K.x, K.y, xs, ve.x, vo.x);
            eval2(I.y, K.z, K.w, xs, ve.y, vo.y);

            __stcs(reinterpret_cast<float2*>(&oe[j0]), ve);
            __stcs(reinterpret_cast<float2*>(&oo[j0]), vo);

            // (3) convert + store staged data
            if (do_stage && g < NSTAGE) {
                __half2 h0 = __floats2half2_rn(se.x, so.x);
                __half2 h1 = __floats2half2_rn(se.y, so.y);
                __half2 h2 = __floats2half2_rn(se.z, so.z);
                __half2 h3 = __floats2half2_rn(se.w, so.w);
                uint4 pk;
                pk.x = *reinterpret_cast<unsigned int*>(&h0);
                pk.y = *reinterpret_cast<unsigned int*>(&h1);
                pk.z = *reinterpret_cast<unsigned int*>(&h2);
                pk.w = *reinterpret_cast<unsigned int*>(&h3);
                *reinterpret_cast<uint4*>(dst + sk) = pk;
            }
        }

        if (tid == 0) s_next[pi ^ 1] = atomicAdd(&g_ctr, 1);
        __syncthreads();

        cur = nxt;
        s ^= 1;
        pi ^= 1;
    }
}

extern "C" void kernel_launch(void* const* d_in, const int* in_sizes, int n_in,
                              void* d_out, int out_size)
{
    const float* x  = (const float*)d_in[0];
    const float* w  = (const float*)d_in[1];
    const void*  ai = d_in[2];
    const void*  bi = d_in[3];
    float* out = (float*)d_out;
    (void)in_sizes; (void)n_in; (void)out_size;

    int nsm = 148;
    cudaDeviceGetAttribute(&nsm, cudaDevAttrMultiProcessorCount, 0);
    const int ncta = nsm;   // 1 CTA per SM

    const int smem_bytes = 2 * IN_DIM * sizeof(__half2);   // 128KB per CTA
    cudaFuncSetAttribute(logic_main_kernel,
                         cudaFuncAttributeMaxDynamicSharedMemorySize, smem_bytes);

    prep_kernel<<<(OUT_DIM + 511) / 512, 512>>>(w, ai, bi, ncta);
    logic_main_kernel<<<ncta, THREADS, smem_bytes>>>(x, out);
}